// round 1
// baseline (speedup 1.0000x reference)
#include <cuda_runtime.h>
#include <cstdint>

// Tensor-train contraction, B=262144 batches, D=32 binary-indexed cores, R=16.
// out[b] = v0(x0) @ M1(x1) @ ... @ M30(x30) @ vlast(x31)
// Factorization: bits split 8/8/8/8 ->
//   UA[256][16]   : v0(x0) @ M1..M7            (bits 0..7)
//   PA[256][16][16]: M8..M15                    (bits 8..15)
//   PB[256][16][16]: M16..M23                   (bits 16..23)
//   WA[256][16]   : M24..M30 @ vlast(x31)       (bits 24..31)
// Compose: U[pa=bits0..15] = UA[pa&255] @ PA[pa>>8]   (65536 x 16 floats)
//          W[ps=bits16..31] = PB[ps&255] @ WA[ps>>8]  (65536 x 16 floats)
// Main: out[b] = dot(U[pa], W[ps])  -- 16 FMA + 128B gather per batch.

#define R16 16

__device__ __align__(16) float g_UA[256 * 16];
__device__ __align__(16) float g_WA[256 * 16];
__device__ __align__(16) float g_PA[256 * 256];
__device__ __align__(16) float g_PB[256 * 256];
__device__ __align__(16) float g_U[65536 * 16];
__device__ __align__(16) float g_W[65536 * 16];

// cores_mid element [i][r][s][bit] at cm[i*512 + r*32 + s*2 + bit]
// core_first [0][r][bit] at cf[r*2 + bit];  core_last [r][0][bit] at cl[r*2 + bit]

__global__ __launch_bounds__(256) void tt_stageA(const float* __restrict__ cf,
                                                 const float* __restrict__ cm,
                                                 const float* __restrict__ cl) {
    int blk = blockIdx.x;
    int tid = threadIdx.x;

    if (blk < 16) {
        // UA: 16 entries per block; threads (entry_local, r)
        __shared__ float v[16][17];
        int el = tid >> 4, r = tid & 15;
        int e = blk * 16 + el;
        v[el][r] = cf[r * 2 + (e & 1)];
        __syncthreads();
        for (int j = 1; j <= 7; j++) {
            int bj = (e >> j) & 1;
            const float* M = cm + (j - 1) * 512;
            float acc = 0.f;
#pragma unroll
            for (int s = 0; s < 16; s++)
                acc += v[el][s] * M[(s * 16 + r) * 2 + bj];  // new[r] = sum_s v[s]*M[s][r]
            __syncthreads();
            v[el][r] = acc;
            __syncthreads();
        }
        g_UA[e * 16 + r] = v[el][r];
    } else if (blk < 32) {
        // WA: suffix vectors, bits 24..31 (bit (i-24) of e = x_i; bit 7 = x31)
        __shared__ float v[16][17];
        int el = tid >> 4, r = tid & 15;
        int e = (blk - 16) * 16 + el;
        v[el][r] = cl[r * 2 + ((e >> 7) & 1)];
        __syncthreads();
        for (int j = 30; j >= 24; j--) {
            int bj = (e >> (j - 24)) & 1;
            const float* M = cm + (j - 1) * 512;
            float acc = 0.f;
#pragma unroll
            for (int s = 0; s < 16; s++)
                acc += M[(r * 16 + s) * 2 + bj] * v[el][s];  // new[r] = sum_s M[r][s]*w[s]
            __syncthreads();
            v[el][r] = acc;
            __syncthreads();
        }
        g_WA[e * 16 + r] = v[el][r];
    } else if (blk < 288) {
        // PA: one entry per block; P = M8(b8) @ ... @ M15(b15); threads (r,c)
        int e = blk - 32;
        int r = tid >> 4, c = tid & 15;
        __shared__ float P[16][17];
        P[r][c] = cm[14 * 512 + (r * 16 + c) * 2 + ((e >> 7) & 1)];  // M15 column c
        __syncthreads();
        for (int j = 14; j >= 8; j--) {
            int bj = (e >> (j - 8)) & 1;
            const float* M = cm + (j - 1) * 512;
            float acc = 0.f;
#pragma unroll
            for (int s = 0; s < 16; s++)
                acc += M[(r * 16 + s) * 2 + bj] * P[s][c];
            __syncthreads();
            P[r][c] = acc;
            __syncthreads();
        }
        g_PA[e * 256 + r * 16 + c] = P[r][c];
    } else {
        // PB: one entry per block; P = M16(b16) @ ... @ M23(b23)
        int e = blk - 288;
        int r = tid >> 4, c = tid & 15;
        __shared__ float P[16][17];
        P[r][c] = cm[22 * 512 + (r * 16 + c) * 2 + ((e >> 7) & 1)];  // M23 column c
        __syncthreads();
        for (int j = 22; j >= 16; j--) {
            int bj = (e >> (j - 16)) & 1;
            const float* M = cm + (j - 1) * 512;
            float acc = 0.f;
#pragma unroll
            for (int s = 0; s < 16; s++)
                acc += M[(r * 16 + s) * 2 + bj] * P[s][c];
            __syncthreads();
            P[r][c] = acc;
            __syncthreads();
        }
        g_PB[e * 256 + r * 16 + c] = P[r][c];
    }
}

__global__ __launch_bounds__(256) void tt_stageB() {
    __shared__ float Pm[256];
    int blk = blockIdx.x;
    int t = threadIdx.x;
    if (blk < 256) {
        // U[(hi<<8)|lo][s] = sum_r UA[lo][r] * PA[hi][r][s]; block=hi, thread=lo
        int hi = blk, lo = t;
        Pm[t] = g_PA[hi * 256 + t];
        __syncthreads();
        float u[16];
#pragma unroll
        for (int r = 0; r < 16; r++) u[r] = g_UA[lo * 16 + r];
        float* dst = &g_U[(((unsigned)hi << 8) | lo) * 16];
#pragma unroll
        for (int s = 0; s < 16; s++) {
            float acc = 0.f;
#pragma unroll
            for (int r = 0; r < 16; r++) acc += u[r] * Pm[r * 16 + s];  // broadcast
            dst[s] = acc;
        }
    } else {
        // W[(hi<<8)|lo][r] = sum_s PB[lo][r][s] * WA[hi][s]; block=lo, thread=hi
        int lo = blk - 256, hi = t;
        Pm[t] = g_PB[lo * 256 + t];
        __syncthreads();
        float wv[16];
#pragma unroll
        for (int s = 0; s < 16; s++) wv[s] = g_WA[hi * 16 + s];
        float* dst = &g_W[(((unsigned)hi << 8) | lo) * 16];
#pragma unroll
        for (int r = 0; r < 16; r++) {
            float acc = 0.f;
#pragma unroll
            for (int s = 0; s < 16; s++) acc += Pm[r * 16 + s] * wv[s];  // broadcast
            dst[r] = acc;
        }
    }
}

__global__ __launch_bounds__(256) void tt_main(const int* __restrict__ X,
                                               float* __restrict__ out) {
    int b = blockIdx.x * blockDim.x + threadIdx.x;
    const int4* xr = reinterpret_cast<const int4*>(X + (size_t)b * 32);

    int pa = 0, ps = 0;
#pragma unroll
    for (int k = 0; k < 4; k++) {
        int4 q = xr[k];
        pa |= (q.x << (4 * k)) | (q.y << (4 * k + 1)) |
              (q.z << (4 * k + 2)) | (q.w << (4 * k + 3));
    }
#pragma unroll
    for (int k = 0; k < 4; k++) {
        int4 q = xr[4 + k];
        ps |= (q.x << (4 * k)) | (q.y << (4 * k + 1)) |
              (q.z << (4 * k + 2)) | (q.w << (4 * k + 3));
    }

    const float4* up = reinterpret_cast<const float4*>(&g_U[(size_t)pa * 16]);
    const float4* wp = reinterpret_cast<const float4*>(&g_W[(size_t)ps * 16]);
    float acc = 0.f;
#pragma unroll
    for (int k = 0; k < 4; k++) {
        float4 u = up[k];
        float4 w = wp[k];
        acc += u.x * w.x + u.y * w.y + u.z * w.z + u.w * w.w;
    }
    out[b] = acc;
}

extern "C" void kernel_launch(void* const* d_in, const int* in_sizes, int n_in,
                              void* d_out, int out_size) {
    const int* X = (const int*)d_in[0];
    const float* cf = (const float*)d_in[1];
    const float* cm = (const float*)d_in[2];
    const float* cl = (const float*)d_in[3];
    float* out = (float*)d_out;

    tt_stageA<<<544, 256>>>(cf, cm, cl);
    tt_stageB<<<512, 256>>>();
    tt_main<<<out_size / 256, 256>>>(X, out);
}

// round 3
// speedup vs baseline: 1.3524x; 1.3524x over previous
#include <cuda_runtime.h>
#include <cstdint>

// Tensor-train contraction, B=262144, D=32 binary cores, R=16.
// out[b] = v0(x0) @ M1(x1) @ ... @ M30(x30) @ vlast(x31)
// Bits split 8/8/8/8:
//   UA[256][16]    : v0 @ M1..M7        (bits 0..7)
//   PA[256][16][16]: M8..M15            (bits 8..15)
//   PB[256][16][16]: M16..M23           (bits 16..23)
//   WA[256][16]    : M24..M30 @ vlast   (bits 24..31)
// U[bits0..15] = UA[lo] @ PA[hi]   (65536 x 16)
// W[bits16..31] = PB[lo] @ WA[hi]  (65536 x 16)
// out[b] = dot(U[pa], W[ps])

__device__ __align__(128) float g_UA[256 * 16];
__device__ __align__(128) float g_WA[256 * 16];
__device__ __align__(128) float g_PA[256 * 256];
__device__ __align__(128) float g_PB[256 * 256];
__device__ __align__(128) float g_U[65536 * 16];
__device__ __align__(128) float g_W[65536 * 16];

// cores_mid [i][r][s][bit] at cm[i*512 + r*32 + s*2 + bit]   (i = j-1 for M_j)
// core_first [0][r][bit] at cf[r*2+bit];  core_last [r][0][bit] at cl[r*2+bit]

__global__ __launch_bounds__(256) void tt_stageA(const float* __restrict__ cf,
                                                 const float* __restrict__ cm,
                                                 const float* __restrict__ cl) {
    __shared__ float sm[3584 + 2 * 16 * 17];
    float* Ms = sm;
    float (*V)[16][17] = reinterpret_cast<float(*)[16][17]>(sm + 3584);

    int blk = blockIdx.x;
    int tid = threadIdx.x;

    if (blk < 32) {
        // ---- vector chains: UA (blk<16) and WA (blk>=16), 16 entries/block ----
        bool isU = blk < 16;
        int el = tid >> 4, r = tid & 15;
        int e = (isU ? blk : blk - 16) * 16 + el;

        // Preload all 7 matrices, both bit variants (3584 floats).
        // UA chain reads M[s][r] -> natural layout (s*32 + r*2 + bit) is fine.
        // WA chain reads M[r][s] -> transpose on store so sum-index s is the
        // row stride and output index r gives distinct banks.
        int base = isU ? 0 : 23 * 512;
        for (int idx = tid; idx < 3584; idx += 256) {
            float val = cm[base + idx];
            if (isU) {
                Ms[idx] = val;
            } else {
                int j = idx >> 9;
                int row = (idx >> 5) & 15;
                int col = (idx >> 1) & 15;
                int bit = idx & 1;
                Ms[j * 512 + col * 32 + row * 2 + bit] = val;
            }
        }

        int cur = 0;
        if (isU)
            V[cur][el][r] = cf[r * 2 + (e & 1)];
        else
            V[cur][el][r] = cl[r * 2 + ((e >> 7) & 1)];
        __syncthreads();

        if (isU) {
            for (int j = 1; j <= 7; j++) {
                int bj = (e >> j) & 1;
                const float* M = Ms + (j - 1) * 512;
                float acc = 0.f;
#pragma unroll
                for (int s = 0; s < 16; s++)
                    acc += V[cur][el][s] * M[s * 32 + r * 2 + bj];  // new[r]=Σ v[s]M[s][r]
                V[cur ^ 1][el][r] = acc;
                __syncthreads();
                cur ^= 1;
            }
            g_UA[e * 16 + r] = V[cur][el][r];
        } else {
            for (int j = 30; j >= 24; j--) {
                int bj = (e >> (j - 24)) & 1;
                const float* M = Ms + (j - 24) * 512;  // transposed: [s][r]
                float acc = 0.f;
#pragma unroll
                for (int s = 0; s < 16; s++)
                    acc += M[s * 32 + r * 2 + bj] * V[cur][el][s];  // new[r]=Σ M[r][s]w[s]
                V[cur ^ 1][el][r] = acc;
                __syncthreads();
                cur ^= 1;
            }
            g_WA[e * 16 + r] = V[cur][el][r];
        }
    } else {
        // ---- matrix chains: PA (blk in [32,288)) / PB (blk in [288,544)) ----
        int e, jbase;
        float* dst;
        if (blk < 288) { e = blk - 32;  jbase = 8;  dst = g_PA; }
        else           { e = blk - 288; jbase = 16; dst = g_PB; }
        int r = tid >> 4, c = tid & 15;

        // Preload the 8 SELECTED matrices (bits known per block): Ms[jl][r*16+c]
        for (int jl = 0; jl < 8; jl++) {
            int bit = (e >> jl) & 1;
            Ms[jl * 256 + tid] = cm[(jbase + jl - 1) * 512 + r * 32 + c * 2 + bit];
        }
        float (*P)[16][17] = V;
        P[0][r][c] = Ms[7 * 256 + tid];  // init P = M_{jbase+7} (own write, no sync)
        __syncthreads();

        int cur = 0;
        for (int jl = 6; jl >= 0; jl--) {
            float acc = 0.f;
#pragma unroll
            for (int s = 0; s < 16; s++)
                acc += Ms[jl * 256 + r * 16 + s] * P[cur][s][c];  // P_new = M_j @ P
            P[cur ^ 1][r][c] = acc;
            __syncthreads();
            cur ^= 1;
        }
        dst[e * 256 + tid] = P[cur][r][c];
    }
}

__global__ __launch_bounds__(256) void tt_stageB() {
    __shared__ float Pm[256];
    int blk = blockIdx.x;
    int t = threadIdx.x;
    if (blk < 256) {
        // U[(hi<<8)|lo][s] = Σ_r UA[lo][r] * PA[hi][r][s];  block=hi, thread=lo
        int hi = blk, lo = t;
        Pm[t] = g_PA[hi * 256 + t];
        __syncthreads();
        const float4* uap = reinterpret_cast<const float4*>(&g_UA[lo * 16]);
        float u[16];
#pragma unroll
        for (int k = 0; k < 4; k++) {
            float4 q = uap[k];
            u[4 * k] = q.x; u[4 * k + 1] = q.y; u[4 * k + 2] = q.z; u[4 * k + 3] = q.w;
        }
        float res[16];
#pragma unroll
        for (int s = 0; s < 16; s++) {
            float acc = 0.f;
#pragma unroll
            for (int r = 0; r < 16; r++) acc += u[r] * Pm[r * 16 + s];  // smem broadcast
            res[s] = acc;
        }
        float4* dstv = reinterpret_cast<float4*>(&g_U[(((unsigned)hi << 8) | lo) * 16]);
#pragma unroll
        for (int k = 0; k < 4; k++)
            dstv[k] = make_float4(res[4 * k], res[4 * k + 1], res[4 * k + 2], res[4 * k + 3]);
    } else {
        // W[(hi<<8)|lo][r] = Σ_s PB[lo][r][s] * WA[hi][s];  block=lo, thread=hi
        int lo = blk - 256, hi = t;
        Pm[t] = g_PB[lo * 256 + t];
        __syncthreads();
        const float4* wap = reinterpret_cast<const float4*>(&g_WA[hi * 16]);
        float wv[16];
#pragma unroll
        for (int k = 0; k < 4; k++) {
            float4 q = wap[k];
            wv[4 * k] = q.x; wv[4 * k + 1] = q.y; wv[4 * k + 2] = q.z; wv[4 * k + 3] = q.w;
        }
        float res[16];
#pragma unroll
        for (int r = 0; r < 16; r++) {
            float acc = 0.f;
#pragma unroll
            for (int s = 0; s < 16; s++) acc += Pm[r * 16 + s] * wv[s];
            res[r] = acc;
        }
        float4* dstv = reinterpret_cast<float4*>(&g_W[(((unsigned)hi << 8) | lo) * 16]);
#pragma unroll
        for (int k = 0; k < 4; k++)
            dstv[k] = make_float4(res[4 * k], res[4 * k + 1], res[4 * k + 2], res[4 * k + 3]);
    }
}

__global__ __launch_bounds__(256) void tt_main(const int* __restrict__ X,
                                               float* __restrict__ out) {
    int b = blockIdx.x * blockDim.x + threadIdx.x;
    const int4* xr = reinterpret_cast<const int4*>(X + (size_t)b * 32);

    int pa = 0, ps = 0;
#pragma unroll
    for (int k = 0; k < 4; k++) {
        int4 q = xr[k];
        pa |= (q.x << (4 * k)) | (q.y << (4 * k + 1)) |
              (q.z << (4 * k + 2)) | (q.w << (4 * k + 3));
    }
#pragma unroll
    for (int k = 0; k < 4; k++) {
        int4 q = xr[4 + k];
        ps |= (q.x << (4 * k)) | (q.y << (4 * k + 1)) |
              (q.z << (4 * k + 2)) | (q.w << (4 * k + 3));
    }

    const float4* up = reinterpret_cast<const float4*>(&g_U[(size_t)pa * 16]);
    const float4* wp = reinterpret_cast<const float4*>(&g_W[(size_t)ps * 16]);
    float acc = 0.f;
#pragma unroll
    for (int k = 0; k < 4; k++) {
        float4 u = up[k];
        float4 w = wp[k];
        acc += u.x * w.x + u.y * w.y + u.z * w.z + u.w * w.w;
    }
    out[b] = acc;
}

extern "C" void kernel_launch(void* const* d_in, const int* in_sizes, int n_in,
                              void* d_out, int out_size) {
    const int* X = (const int*)d_in[0];
    const float* cf = (const float*)d_in[1];
    const float* cm = (const float*)d_in[2];
    const float* cl = (const float*)d_in[3];
    float* out = (float*)d_out;

    tt_stageA<<<544, 256>>>(cf, cm, cl);
    tt_stageB<<<512, 256>>>();
    tt_main<<<out_size / 256, 256>>>(X, out);
}

// round 4
// speedup vs baseline: 1.5575x; 1.1517x over previous
#include <cuda_runtime.h>
#include <cstdint>

// Tensor-train contraction, B=262144, D=32 binary cores, R=16.
// out[b] = v0(x0) @ M1(x1) @ ... @ M30(x30) @ vlast(x31)
// Bits split 8/8/8/8:
//   UA[256][16]    : v0 @ M1..M7        (bits 0..7)
//   PA[256][16][16]: M8..M15            (bits 8..15)
//   PB[256][16][16]: M16..M23           (bits 16..23)
//   WA[256][16]    : M24..M30 @ vlast   (bits 24..31)
// U[bits0..15] = UA[lo] @ PA[hi]   (65536 x 16)
// W[bits16..31] = PB[lo] @ WA[hi]  (65536 x 16)
// out[b] = dot(U[pa], W[ps])

__device__ __align__(128) float g_UA[256 * 16];
__device__ __align__(128) float g_WA[256 * 16];
__device__ __align__(128) float g_PA[256 * 256];
__device__ __align__(128) float g_PB[256 * 256];
__device__ __align__(128) float g_U[65536 * 16];
__device__ __align__(128) float g_W[65536 * 16];

// cores_mid [i][r][s][bit] at cm[i*512 + r*32 + s*2 + bit]   (i = j-1 for M_j)
// core_first [0][r][bit] at cf[r*2+bit];  core_last [r][0][bit] at cl[r*2+bit]

// Grid layout: blk 0..15 UA, 16..31 WA, 32..95 PA (4 entries/blk), 96..159 PB.
__global__ __launch_bounds__(256) void tt_stageA(const float* __restrict__ cf,
                                                 const float* __restrict__ cm,
                                                 const float* __restrict__ cl) {
    __shared__ float sm[8 * 512 + 2 * 4 * 16 * 17];  // 25KB

    int blk = blockIdx.x;
    int tid = threadIdx.x;

    if (blk < 32) {
        // ---- vector chains: UA (blk<16) and WA (blk>=16), 16 entries/block ----
        float* Ms = sm;
        float (*V)[16][17] = reinterpret_cast<float(*)[16][17]>(sm + 3584);
        bool isU = blk < 16;
        int el = tid >> 4, r = tid & 15;
        int e = (isU ? blk : blk - 16) * 16 + el;

        // Preload 7 matrices, both bit variants (3584 floats). WA chain is
        // transposed on store so its read pattern matches UA's.
        int base = isU ? 0 : 23 * 512;
        for (int idx = tid; idx < 3584; idx += 256) {
            float val = cm[base + idx];
            if (isU) {
                Ms[idx] = val;
            } else {
                int j = idx >> 9;
                int row = (idx >> 5) & 15;
                int col = (idx >> 1) & 15;
                int bit = idx & 1;
                Ms[j * 512 + col * 32 + row * 2 + bit] = val;
            }
        }

        int cur = 0;
        if (isU)
            V[cur][el][r] = cf[r * 2 + (e & 1)];
        else
            V[cur][el][r] = cl[r * 2 + ((e >> 7) & 1)];
        __syncthreads();

        if (isU) {
            for (int j = 1; j <= 7; j++) {
                int bj = (e >> j) & 1;
                const float* M = Ms + (j - 1) * 512;
                float acc = 0.f;
#pragma unroll
                for (int s = 0; s < 16; s++)
                    acc += V[cur][el][s] * M[s * 32 + r * 2 + bj];
                V[cur ^ 1][el][r] = acc;
                __syncthreads();
                cur ^= 1;
            }
            g_UA[e * 16 + r] = V[cur][el][r];
        } else {
            for (int j = 30; j >= 24; j--) {
                int bj = (e >> (j - 24)) & 1;
                const float* M = Ms + (j - 24) * 512;  // transposed [s][r]
                float acc = 0.f;
#pragma unroll
                for (int s = 0; s < 16; s++)
                    acc += M[s * 32 + r * 2 + bj] * V[cur][el][s];
                V[cur ^ 1][el][r] = acc;
                __syncthreads();
                cur ^= 1;
            }
            g_WA[e * 16 + r] = V[cur][el][r];
        }
    } else {
        // ---- matrix chains: 4 entries per block for ILP ----
        int e0, jofs;
        float* dst;
        if (blk < 96) { e0 = (blk - 32) * 4;  jofs = 7 * 512;  dst = g_PA; }
        else          { e0 = (blk - 96) * 4;  jofs = 15 * 512; dst = g_PB; }
        int r = tid >> 4, c = tid & 15;

        // Ms[jl][bit][r*16+s], 4096 floats (both variants of all 8 matrices)
        float* Ms = sm;
        float (*P)[4][16 * 17] = reinterpret_cast<float(*)[4][16 * 17]>(sm + 4096);

        for (int idx = tid; idx < 4096; idx += 256) {
            int jl = idx >> 9;
            int row = (idx >> 5) & 15;
            int s = (idx >> 1) & 15;
            int bit = idx & 1;
            Ms[jl * 512 + bit * 256 + row * 16 + s] = cm[jofs + idx];
        }
        __syncthreads();

        // init P_e = M_{top} (bit 7 of e)
#pragma unroll
        for (int ei = 0; ei < 4; ei++) {
            int bit = ((e0 + ei) >> 7) & 1;
            P[0][ei][r * 17 + c] = Ms[7 * 512 + bit * 256 + tid];
        }
        __syncthreads();

        int cur = 0;
        for (int jl = 6; jl >= 0; jl--) {
            float acc[4];
#pragma unroll
            for (int ei = 0; ei < 4; ei++) {
                int bit = ((e0 + ei) >> jl) & 1;
                const float4* Mrow =
                    reinterpret_cast<const float4*>(&Ms[jl * 512 + bit * 256 + r * 16]);
                float4 m0 = Mrow[0], m1 = Mrow[1], m2 = Mrow[2], m3 = Mrow[3];
                const float* Pc = &P[cur][ei][c];
                float a = 0.f;
                a += m0.x * Pc[0 * 17] + m0.y * Pc[1 * 17] + m0.z * Pc[2 * 17] + m0.w * Pc[3 * 17];
                a += m1.x * Pc[4 * 17] + m1.y * Pc[5 * 17] + m1.z * Pc[6 * 17] + m1.w * Pc[7 * 17];
                a += m2.x * Pc[8 * 17] + m2.y * Pc[9 * 17] + m2.z * Pc[10 * 17] + m2.w * Pc[11 * 17];
                a += m3.x * Pc[12 * 17] + m3.y * Pc[13 * 17] + m3.z * Pc[14 * 17] + m3.w * Pc[15 * 17];
                acc[ei] = a;
            }
            __syncthreads();
#pragma unroll
            for (int ei = 0; ei < 4; ei++) P[cur ^ 1][ei][r * 17 + c] = acc[ei];
            __syncthreads();
            cur ^= 1;
        }
#pragma unroll
        for (int ei = 0; ei < 4; ei++)
            dst[(e0 + ei) * 256 + tid] = P[cur][ei][r * 17 + c];
    }
}

__global__ __launch_bounds__(256) void tt_stageB() {
    __shared__ float Pm[256];
    int blk = blockIdx.x;
    int t = threadIdx.x;
    const float4* PmV = reinterpret_cast<const float4*>(Pm);

    if (blk < 256) {
        // U[(hi<<8)|lo][s] = Σ_r UA[lo][r] * PA[hi][r][s];  block=hi, thread=lo
        int hi = blk, lo = t;
        Pm[t] = g_PA[hi * 256 + t];
        __syncthreads();
        const float4* uap = reinterpret_cast<const float4*>(&g_UA[lo * 16]);
        float u[16];
#pragma unroll
        for (int k = 0; k < 4; k++) {
            float4 q = uap[k];
            u[4 * k] = q.x; u[4 * k + 1] = q.y; u[4 * k + 2] = q.z; u[4 * k + 3] = q.w;
        }
        float res[16];
#pragma unroll
        for (int s = 0; s < 16; s++) res[s] = 0.f;
#pragma unroll
        for (int r = 0; r < 16; r++) {
            float4 m0 = PmV[r * 4 + 0], m1 = PmV[r * 4 + 1];
            float4 m2 = PmV[r * 4 + 2], m3 = PmV[r * 4 + 3];
            float ur = u[r];
            res[0] += ur * m0.x;  res[1] += ur * m0.y;  res[2] += ur * m0.z;  res[3] += ur * m0.w;
            res[4] += ur * m1.x;  res[5] += ur * m1.y;  res[6] += ur * m1.z;  res[7] += ur * m1.w;
            res[8] += ur * m2.x;  res[9] += ur * m2.y;  res[10] += ur * m2.z; res[11] += ur * m2.w;
            res[12] += ur * m3.x; res[13] += ur * m3.y; res[14] += ur * m3.z; res[15] += ur * m3.w;
        }
        float4* dstv = reinterpret_cast<float4*>(&g_U[(((unsigned)hi << 8) | lo) * 16]);
#pragma unroll
        for (int k = 0; k < 4; k++)
            dstv[k] = make_float4(res[4 * k], res[4 * k + 1], res[4 * k + 2], res[4 * k + 3]);
    } else {
        // W[(hi<<8)|lo][r] = Σ_s PB[lo][r][s] * WA[hi][s];  block=lo, thread=hi
        int lo = blk - 256, hi = t;
        Pm[t] = g_PB[lo * 256 + t];
        __syncthreads();
        const float4* wap = reinterpret_cast<const float4*>(&g_WA[hi * 16]);
        float4 w0 = wap[0], w1 = wap[1], w2 = wap[2], w3 = wap[3];
        float res[16];
#pragma unroll
        for (int r = 0; r < 16; r++) {
            float4 m0 = PmV[r * 4 + 0], m1 = PmV[r * 4 + 1];
            float4 m2 = PmV[r * 4 + 2], m3 = PmV[r * 4 + 3];
            float a = m0.x * w0.x + m0.y * w0.y + m0.z * w0.z + m0.w * w0.w;
            a += m1.x * w1.x + m1.y * w1.y + m1.z * w1.z + m1.w * w1.w;
            a += m2.x * w2.x + m2.y * w2.y + m2.z * w2.z + m2.w * w2.w;
            a += m3.x * w3.x + m3.y * w3.y + m3.z * w3.z + m3.w * w3.w;
            res[r] = a;
        }
        float4* dstv = reinterpret_cast<float4*>(&g_W[(((unsigned)hi << 8) | lo) * 16]);
#pragma unroll
        for (int k = 0; k < 4; k++)
            dstv[k] = make_float4(res[4 * k], res[4 * k + 1], res[4 * k + 2], res[4 * k + 3]);
    }
}

__global__ __launch_bounds__(256) void tt_main(const int* __restrict__ X,
                                               float* __restrict__ out) {
    int gtid = blockIdx.x * blockDim.x + threadIdx.x;
    int warp = gtid >> 5;
    int lane = threadIdx.x & 31;

    // Warp covers 32 consecutive batches. Iteration i: lane l loads X[b_i, l]
    // (coalesced 128B) and one ballot packs the whole 32-bit index.
    size_t base = (size_t)warp * 32 * 32;
    unsigned m = 0;
#pragma unroll
    for (int i = 0; i < 32; i++) {
        int x = __ldg(&X[base + (size_t)i * 32 + lane]);
        unsigned bm = __ballot_sync(0xFFFFFFFFu, x != 0);
        if (i == lane) m = bm;
    }
    unsigned pa = m & 0xFFFFu;
    unsigned ps = m >> 16;

    const float4* up = reinterpret_cast<const float4*>(&g_U[(size_t)pa * 16]);
    const float4* wp = reinterpret_cast<const float4*>(&g_W[(size_t)ps * 16]);
    float acc = 0.f;
#pragma unroll
    for (int k = 0; k < 4; k++) {
        float4 u = up[k];
        float4 w = wp[k];
        acc += u.x * w.x + u.y * w.y + u.z * w.z + u.w * w.w;
    }
    out[warp * 32 + lane] = acc;
}

extern "C" void kernel_launch(void* const* d_in, const int* in_sizes, int n_in,
                              void* d_out, int out_size) {
    const int* X = (const int*)d_in[0];
    const float* cf = (const float*)d_in[1];
    const float* cm = (const float*)d_in[2];
    const float* cl = (const float*)d_in[3];
    float* out = (float*)d_out;

    tt_stageA<<<160, 256>>>(cf, cm, cl);
    tt_stageB<<<512, 256>>>();
    tt_main<<<out_size / 256, 256>>>(X, out);
}

// round 7
// speedup vs baseline: 1.6318x; 1.0477x over previous
#include <cuda_runtime.h>
#include <cstdint>

// Tensor-train contraction, B=262144, D=32 binary cores, R=16.
// out[b] = v0(x0) @ M1(x1) @ ... @ M30(x30) @ vlast(x31)
// Bits split 8/8/8/8:
//   UA[256][16]    : v0 @ M1..M7        (bits 0..7)
//   PA[256][16][16]: M8 @ ... @ M15     (bits 8..15)
//   PB[256][16][16]: M16 @ ... @ M23    (bits 16..23)
//   WA[256][16]    : M24..M30 @ vlast   (bits 24..31)
// U[bits0..15] = UA[lo] @ PA[hi]   (65536 x 16)
// W[bits16..31] = PB[lo] @ WA[hi]  (65536 x 16)
// out[b] = dot(U[pa], W[ps])

__device__ __align__(128) float g_UA[256 * 16];
__device__ __align__(128) float g_WA[256 * 16];
__device__ __align__(128) float g_PA[256 * 256];
__device__ __align__(128) float g_PB[256 * 256];
__device__ __align__(128) float g_U[65536 * 16];
__device__ __align__(128) float g_W[65536 * 16];

// cores_mid M_j (j=1..30) element [r][s][bit] at cm[(j-1)*512 + r*32 + s*2 + bit]
// core_first [0][r][bit] at cf[r*2+bit];  core_last [r][0][bit] at cl[r*2+bit]

// Grid: 544 blocks x 32 threads.
//   blk 0..15   : UA, 16 entries each (2 threads/entry)
//   blk 16..31  : WA, 16 entries each
//   blk 32..287 : PA, 1 entry each (warp-per-entry, register P + shfl)
//   blk 288..543: PB, 1 entry each
__global__ __launch_bounds__(32) void tt_stageA(const float* __restrict__ cf,
                                                const float* __restrict__ cm,
                                                const float* __restrict__ cl) {
    __shared__ float Ms[3584];  // 14KB max (vector branch); matrix uses 2048
    const float2* cm2 = reinterpret_cast<const float2*>(cm);
    int blk = blockIdx.x;
    int t = threadIdx.x;

    if (blk >= 32) {
        // ---------- matrix chains: warp-per-entry ----------
        int e, jbase;
        float* dst;
        if (blk < 288) { e = blk - 32;  jbase = 8;  dst = g_PA; }
        else           { e = blk - 288; jbase = 16; dst = g_PB; }

        // Preload the 8 SELECTED matrices: Ms[jl*256 + r*16 + s] = M_{jbase+jl}[r][s]
        for (int idx = t; idx < 2048; idx += 32) {
            int jl = idx >> 8;
            int rc = idx & 255;
            float2 v2 = cm2[(jbase + jl - 1) * 256 + rc];
            Ms[idx] = ((e >> jl) & 1) ? v2.y : v2.x;
        }
        __syncwarp();

        // Thread t owns P[8*rh + k][c], k=0..7, rh = t>>4, c = t&15.
        int rh = t >> 4, c = t & 15;
        float P[8];
#pragma unroll
        for (int k = 0; k < 8; k++)
            P[k] = Ms[7 * 256 + (8 * rh + k) * 16 + c];  // init P = M_{jbase+7}

        for (int jl = 6; jl >= 0; jl--) {
            // full column c: own half + partner half (t^16)
            float col[16];
#pragma unroll
            for (int k = 0; k < 8; k++) {
                float o = __shfl_xor_sync(0xFFFFFFFFu, P[k], 16);
                if (rh == 0) { col[k] = P[k];  col[8 + k] = o; }
                else         { col[k] = o;     col[8 + k] = P[k]; }
            }
            float nxt[8];
#pragma unroll
            for (int k = 0; k < 8; k++) {
                const float4* Mr =
                    reinterpret_cast<const float4*>(&Ms[jl * 256 + (8 * rh + k) * 16]);
                float4 m0 = Mr[0], m1 = Mr[1], m2 = Mr[2], m3 = Mr[3];
                float a;
                a  = m0.x * col[0]  + m0.y * col[1]  + m0.z * col[2]  + m0.w * col[3];
                a += m1.x * col[4]  + m1.y * col[5]  + m1.z * col[6]  + m1.w * col[7];
                a += m2.x * col[8]  + m2.y * col[9]  + m2.z * col[10] + m2.w * col[11];
                a += m3.x * col[12] + m3.y * col[13] + m3.z * col[14] + m3.w * col[15];
                nxt[k] = a;
            }
#pragma unroll
            for (int k = 0; k < 8; k++) P[k] = nxt[k];
        }
#pragma unroll
        for (int k = 0; k < 8; k++)
            dst[e * 256 + (8 * rh + k) * 16 + c] = P[k];
    } else {
        // ---------- vector chains: 16 entries/block, 2 threads/entry ----------
        bool isU = blk < 16;
        int el = t >> 1, half = t & 1;
        int e = (isU ? blk : blk - 16) * 16 + el;

        // Msm[jj*512 + bit*256 + s*16 + r], jj = chain-step order, r contiguous.
        // UA step jj uses M_{jj+1}[s][r]  (new[r] = sum_s v[s] M[s][r])
        // WA step jj uses M_{30-jj}[r][s] (new[r] = sum_s M[r][s] v[s]) -> transposed
        for (int idx = t; idx < 1792; idx += 32) {
            int jj = idx >> 8;
            int a = (idx >> 4) & 15;   // s
            int b = idx & 15;          // r
            float2 v2 = isU ? cm2[jj * 256 + a * 16 + b]           // M_{jj+1}[s=a][r=b]
                            : cm2[(29 - jj) * 256 + b * 16 + a];   // M_{30-jj}[r=b][s=a]
            Ms[jj * 512 + 0 * 256 + a * 16 + b] = v2.x;
            Ms[jj * 512 + 1 * 256 + a * 16 + b] = v2.y;
        }
        __syncwarp();

        // v half in registers: thread owns v[8*half + k]
        float v[8];
#pragma unroll
        for (int k = 0; k < 8; k++) {
            int r = 8 * half + k;
            v[k] = isU ? cf[r * 2 + (e & 1)] : cl[r * 2 + ((e >> 7) & 1)];
        }

        for (int jj = 0; jj < 7; jj++) {
            int bit = isU ? ((e >> (jj + 1)) & 1) : ((e >> (6 - jj)) & 1);
            float col[16];
#pragma unroll
            for (int k = 0; k < 8; k++) {
                float o = __shfl_xor_sync(0xFFFFFFFFu, v[k], 1);
                if (half == 0) { col[k] = v[k]; col[8 + k] = o; }
                else           { col[k] = o;    col[8 + k] = v[k]; }
            }
            float nxt[8];
#pragma unroll
            for (int k = 0; k < 8; k++) nxt[k] = 0.f;
            const float* Mb = &Ms[jj * 512 + bit * 256];
#pragma unroll
            for (int s = 0; s < 16; s++) {
                const float4* Mr = reinterpret_cast<const float4*>(&Mb[s * 16 + 8 * half]);
                float4 m0 = Mr[0], m1 = Mr[1];
                float cs = col[s];
                nxt[0] += cs * m0.x; nxt[1] += cs * m0.y;
                nxt[2] += cs * m0.z; nxt[3] += cs * m0.w;
                nxt[4] += cs * m1.x; nxt[5] += cs * m1.y;
                nxt[6] += cs * m1.z; nxt[7] += cs * m1.w;
            }
#pragma unroll
            for (int k = 0; k < 8; k++) v[k] = nxt[k];
        }
        float* dst = isU ? g_UA : g_WA;
#pragma unroll
        for (int k = 0; k < 8; k++)
            dst[e * 16 + 8 * half + k] = v[k];
    }
}

__global__ __launch_bounds__(256) void tt_stageB() {
    __shared__ float Pm[256];
    int blk = blockIdx.x;
    int t = threadIdx.x;
    const float4* PmV = reinterpret_cast<const float4*>(Pm);

    if (blk < 256) {
        // U[(hi<<8)|lo][s] = sum_r UA[lo][r] * PA[hi][r][s];  block=hi, thread=lo
        int hi = blk, lo = t;
        Pm[t] = g_PA[hi * 256 + t];
        __syncthreads();
        const float4* uap = reinterpret_cast<const float4*>(&g_UA[lo * 16]);
        float u[16];
#pragma unroll
        for (int k = 0; k < 4; k++) {
            float4 q = uap[k];
            u[4 * k] = q.x; u[4 * k + 1] = q.y; u[4 * k + 2] = q.z; u[4 * k + 3] = q.w;
        }
        float res[16];
#pragma unroll
        for (int s = 0; s < 16; s++) res[s] = 0.f;
#pragma unroll
        for (int r = 0; r < 16; r++) {
            float4 m0 = PmV[r * 4 + 0], m1 = PmV[r * 4 + 1];
            float4 m2 = PmV[r * 4 + 2], m3 = PmV[r * 4 + 3];
            float ur = u[r];
            res[0] += ur * m0.x;  res[1] += ur * m0.y;  res[2] += ur * m0.z;  res[3] += ur * m0.w;
            res[4] += ur * m1.x;  res[5] += ur * m1.y;  res[6] += ur * m1.z;  res[7] += ur * m1.w;
            res[8] += ur * m2.x;  res[9] += ur * m2.y;  res[10] += ur * m2.z; res[11] += ur * m2.w;
            res[12] += ur * m3.x; res[13] += ur * m3.y; res[14] += ur * m3.z; res[15] += ur * m3.w;
        }
        float4* dstv = reinterpret_cast<float4*>(&g_U[(((unsigned)hi << 8) | lo) * 16]);
#pragma unroll
        for (int k = 0; k < 4; k++)
            dstv[k] = make_float4(res[4 * k], res[4 * k + 1], res[4 * k + 2], res[4 * k + 3]);
    } else {
        // W[(hi<<8)|lo][r] = sum_s PB[lo][r][s] * WA[hi][s];  block=lo, thread=hi
        int lo = blk - 256, hi = t;
        Pm[t] = g_PB[lo * 256 + t];
        __syncthreads();
        const float4* wap = reinterpret_cast<const float4*>(&g_WA[hi * 16]);
        float4 w0 = wap[0], w1 = wap[1], w2 = wap[2], w3 = wap[3];
        float res[16];
#pragma unroll
        for (int r = 0; r < 16; r++) {
            float4 m0 = PmV[r * 4 + 0], m1 = PmV[r * 4 + 1];
            float4 m2 = PmV[r * 4 + 2], m3 = PmV[r * 4 + 3];
            float a = m0.x * w0.x + m0.y * w0.y + m0.z * w0.z + m0.w * w0.w;
            a += m1.x * w1.x + m1.y * w1.y + m1.z * w1.z + m1.w * w1.w;
            a += m2.x * w2.x + m2.y * w2.y + m2.z * w2.z + m2.w * w2.w;
            a += m3.x * w3.x + m3.y * w3.y + m3.z * w3.z + m3.w * w3.w;
            res[r] = a;
        }
        float4* dstv = reinterpret_cast<float4*>(&g_W[(((unsigned)hi << 8) | lo) * 16]);
#pragma unroll
        for (int k = 0; k < 4; k++)
            dstv[k] = make_float4(res[4 * k], res[4 * k + 1], res[4 * k + 2], res[4 * k + 3]);
    }
}

__global__ __launch_bounds__(256) void tt_main(const int* __restrict__ X,
                                               float* __restrict__ out) {
    int gtid = blockIdx.x * blockDim.x + threadIdx.x;
    int warp = gtid >> 5;
    int lane = threadIdx.x & 31;

    // Warp covers 32 consecutive batches; lane l loads X[b_i, l] (coalesced
    // 128B per iter) and one ballot packs the whole 32-bit index.
    size_t base = (size_t)warp * 32 * 32;
    unsigned m = 0;
#pragma unroll
    for (int i = 0; i < 32; i++) {
        int x = __ldg(&X[base + (size_t)i * 32 + lane]);
        unsigned bm = __ballot_sync(0xFFFFFFFFu, x != 0);
        if (i == lane) m = bm;
    }
    unsigned pa = m & 0xFFFFu;
    unsigned ps = m >> 16;

    const float4* up = reinterpret_cast<const float4*>(&g_U[(size_t)pa * 16]);
    const float4* wp = reinterpret_cast<const float4*>(&g_W[(size_t)ps * 16]);
    float acc = 0.f;
#pragma unroll
    for (int k = 0; k < 4; k++) {
        float4 u = up[k];
        float4 w = wp[k];
        acc += u.x * w.x + u.y * w.y + u.z * w.z + u.w * w.w;
    }
    out[warp * 32 + lane] = acc;
}

extern "C" void kernel_launch(void* const* d_in, const int* in_sizes, int n_in,
                              void* d_out, int out_size) {
    const int* X = (const int*)d_in[0];
    const float* cf = (const float*)d_in[1];
    const float* cm = (const float*)d_in[2];
    const float* cl = (const float*)d_in[3];
    float* out = (float*)d_out;

    tt_stageA<<<544, 32>>>(cf, cm, cl);
    tt_stageB<<<512, 256>>>();
    tt_main<<<out_size / 256, 256>>>(X, out);
}

// round 8
// speedup vs baseline: 1.8780x; 1.1509x over previous
#include <cuda_runtime.h>
#include <cstdint>

// Tensor-train contraction, B=262144, D=32 binary cores, R=16.
// out[b] = v0(x0) @ M1(x1) @ ... @ M30(x30) @ w31(x31)
//
// 4-bit group tables (product doubling):
//   uv4[16]  = v0(x0)@M1@M2@M3          (bits 0..3)    row vector
//   TU[16]   = M4@M5@M6@M7              (bits 4..7)
//   Tq0[16]  = M8..M11    (bits 8..11)
//   Tq1[16]  = M12..M15   (bits 12..15)
//   Tq2[16]  = M16..M19   (bits 16..19)
//   Tq3[16]  = M20..M23   (bits 20..23)
//   TW[16]   = M24..M27   (bits 24..27)
//   wv4[16]  = M28@M29@M30@w31(x31)     (bits 28..31)  column vector
// A2:  UA[lo8] = uv4[lo8&15] @ TU[lo8>>4]     (256 x 16)
//      WA[e8]  = TW[e8&15]  @ wv4[e8>>4]      (256 x 16)
// B:   U[pa16] = UA[pa&255] @ (Tq0[(pa>>8)&15] @ Tq1[pa>>12])   (65536 x 16)
//      W[ps16] = (Tq2[ps&15] @ Tq3[(ps>>4)&15]) @ WA[ps>>8]     (65536 x 16)
// main: out[b] = dot(U[pa], W[ps])

__device__ __align__(128) float g_uv4[16 * 16];
__device__ __align__(128) float g_wv4[16 * 16];
__device__ __align__(128) float g_TU[16 * 256];
__device__ __align__(128) float g_TW[16 * 256];
__device__ __align__(128) float g_Tq[4][16 * 256];
__device__ __align__(128) float g_UA[256 * 16];
__device__ __align__(128) float g_WA[256 * 16];
__device__ __align__(128) float g_U[65536 * 16];
__device__ __align__(128) float g_W[65536 * 16];

// cores_mid M_j (j=1..30) element [r][s][bit] at cm[(j-1)*512 + r*32 + s*2 + bit]
//   -> as float2: cm2[(j-1)*256 + r*16 + s], .x = bit0, .y = bit1
// core_first [0][r][bit] at cf[r*2+bit];  core_last [r][0][bit] at cl[r*2+bit]

// Grid: 98 blocks x 256.
//   blk 0: uv4 (16 entries), blk 1: wv4 (16 entries)
//   blk 2..97: matrix 4-chain products, pid=blk-2, table=pid>>4, combo e=pid&15
//     tables: 0:TU(j=4..7) 1:Tq0(8..11) 2:Tq1(12..15) 3:Tq2(16..19) 4:Tq3(20..23) 5:TW(24..27)
__global__ __launch_bounds__(256) void tt_A(const float* __restrict__ cf,
                                            const float* __restrict__ cm,
                                            const float* __restrict__ cl) {
    __shared__ float sm[2080];
    const float2* cm2 = reinterpret_cast<const float2*>(cm);
    int blk = blockIdx.x;
    int tid = threadIdx.x;

    if (blk < 2) {
        // ---- vector 4-chains ----
        // smem: Msm[jj][bit][s*16+r] (jj=0..2), 1536 floats; V ping-pong after.
        float (*V)[16][17] = reinterpret_cast<float(*)[16][17]>(sm + 1536);
        bool isU = (blk == 0);
        for (int idx = tid; idx < 768; idx += 256) {
            int jj = idx >> 8;
            int rs = idx & 255;
            if (isU) {
                // step jj applies M_{jj+1}; need element [s][r] at smem [s*16+r]:
                // cm2[jj*256 + s*16 + r] = M_{jj+1}[s][r]; rs = s*16+r directly.
                float2 v2 = cm2[jj * 256 + rs];
                sm[jj * 512 + 0 * 256 + rs] = v2.x;
                sm[jj * 512 + 1 * 256 + rs] = v2.y;
            } else {
                // step jj applies M_{30-jj}; need element [r][s] at smem [s*16+r].
                int r = rs >> 4, s = rs & 15;
                float2 v2 = cm2[(29 - jj) * 256 + rs];  // element [r][s]
                sm[jj * 512 + 0 * 256 + s * 16 + r] = v2.x;
                sm[jj * 512 + 1 * 256 + s * 16 + r] = v2.y;
            }
        }
        int e = tid >> 4, r = tid & 15;
        V[0][e][r] = isU ? cf[r * 2 + (e & 1)] : cl[r * 2 + ((e >> 3) & 1)];
        __syncthreads();
        int cur = 0;
        for (int jj = 0; jj < 3; jj++) {
            int bit = isU ? ((e >> (jj + 1)) & 1) : ((e >> (2 - jj)) & 1);
            const float* M = &sm[jj * 512 + bit * 256];
            float a = 0.f;
#pragma unroll
            for (int s = 0; s < 16; s++) a += V[cur][e][s] * M[s * 16 + r];
            V[cur ^ 1][e][r] = a;
            __syncthreads();
            cur ^= 1;
        }
        float* dst = isU ? g_uv4 : g_wv4;
        dst[e * 16 + r] = V[cur][e][r];
    } else {
        // ---- matrix 4-chain products ----
        int pid = blk - 2;
        int tbl = pid >> 4, e = pid & 15;
        int jbase = (tbl == 0) ? 4 : (tbl == 5) ? 24 : 8 + (tbl - 1) * 4;
        float* dst = (tbl == 0) ? g_TU : (tbl == 5) ? g_TW : g_Tq[tbl - 1];

        float* Msel = sm;  // [jl][r*16+s], 1024 floats (natural [r][s])
        float (*P)[16 * 17] = reinterpret_cast<float(*)[16 * 17]>(sm + 1024);
#pragma unroll
        for (int jl = 0; jl < 4; jl++) {
            float2 v2 = cm2[(jbase + jl - 1) * 256 + tid];
            Msel[jl * 256 + tid] = ((e >> jl) & 1) ? v2.y : v2.x;
        }
        int r = tid >> 4, c = tid & 15;
        __syncthreads();
        P[0][r * 17 + c] = Msel[3 * 256 + tid];  // P = M_{jbase+3}
        __syncthreads();
        int cur = 0;
        for (int jl = 2; jl >= 0; jl--) {
            float a = 0.f;
#pragma unroll
            for (int s = 0; s < 16; s++)
                a += Msel[jl * 256 + r * 16 + s] * P[cur][s * 17 + c];
            P[cur ^ 1][r * 17 + c] = a;
            __syncthreads();
            cur ^= 1;
        }
        dst[e * 256 + tid] = P[cur][r * 17 + c];  // row-major [r][c]
    }
}

// Grid 32 x 256: blk 0..15 UA, blk 16..31 WA.
__global__ __launch_bounds__(256) void tt_A2() {
    __shared__ float Ts[256];
    __shared__ float vs[256];
    int blk = blockIdx.x;
    int tid = threadIdx.x;
    int el = tid >> 4, r = tid & 15;
    if (blk < 16) {
        // UA[lo=blk*16+el][r] = sum_s uv4[el][s] * TU[blk][s][r]
        Ts[tid] = g_TU[blk * 256 + tid];  // [s][r] read pattern = natural rowmajor index s*16+r
        vs[tid] = g_uv4[tid];
        __syncthreads();
        float a = 0.f;
#pragma unroll
        for (int s = 0; s < 16; s++) a += vs[el * 16 + s] * Ts[s * 16 + r];
        g_UA[(blk * 16 + el) * 16 + r] = a;
    } else {
        // WA[e=el*16+b][r] = sum_s TW[b][r][s] * wv4[el][s];  b = blk-16
        int b = blk - 16;
        int rr = tid >> 4, ss = tid & 15;
        Ts[ss * 16 + rr] = g_TW[b * 256 + tid];  // transpose: Ts[s*16+r] = TW[b][r][s]
        vs[tid] = g_wv4[tid];
        __syncthreads();
        float a = 0.f;
#pragma unroll
        for (int s = 0; s < 16; s++) a += Ts[s * 16 + r] * vs[el * 16 + s];
        g_WA[(el * 16 + b) * 16 + r] = a;
    }
}

__global__ __launch_bounds__(256) void tt_B() {
    __shared__ float As[256];
    __shared__ float Bs[256];
    __shared__ __align__(16) float Pm[256];
    int blk = blockIdx.x;
    int t = threadIdx.x;
    int r = t >> 4, c = t & 15;
    const float4* PmV = reinterpret_cast<const float4*>(Pm);

    if (blk < 256) {
        // PA[hi] = Tq0[hi&15] @ Tq1[hi>>4];  U[(hi<<8)|lo][s] = sum_r UA[lo][r]*PA[hi][r][s]
        int hi = blk, lo = t;
        As[t] = g_Tq[0][(hi & 15) * 256 + t];
        Bs[t] = g_Tq[1][(hi >> 4) * 256 + t];
        __syncthreads();
        float pa = 0.f;
#pragma unroll
        for (int s = 0; s < 16; s++) pa += As[r * 16 + s] * Bs[s * 16 + c];
        Pm[t] = pa;  // Pm[r][c]
        __syncthreads();

        const float4* uap = reinterpret_cast<const float4*>(&g_UA[lo * 16]);
        float u[16];
#pragma unroll
        for (int k = 0; k < 4; k++) {
            float4 q = uap[k];
            u[4 * k] = q.x; u[4 * k + 1] = q.y; u[4 * k + 2] = q.z; u[4 * k + 3] = q.w;
        }
        float res[16];
#pragma unroll
        for (int s = 0; s < 16; s++) res[s] = 0.f;
#pragma unroll
        for (int rr = 0; rr < 16; rr++) {
            float4 m0 = PmV[rr * 4 + 0], m1 = PmV[rr * 4 + 1];
            float4 m2 = PmV[rr * 4 + 2], m3 = PmV[rr * 4 + 3];
            float ur = u[rr];
            res[0] += ur * m0.x;  res[1] += ur * m0.y;  res[2] += ur * m0.z;  res[3] += ur * m0.w;
            res[4] += ur * m1.x;  res[5] += ur * m1.y;  res[6] += ur * m1.z;  res[7] += ur * m1.w;
            res[8] += ur * m2.x;  res[9] += ur * m2.y;  res[10] += ur * m2.z; res[11] += ur * m2.w;
            res[12] += ur * m3.x; res[13] += ur * m3.y; res[14] += ur * m3.z; res[15] += ur * m3.w;
        }
        float4* dstv = reinterpret_cast<float4*>(&g_U[(((unsigned)hi << 8) | lo) * 16]);
#pragma unroll
        for (int k = 0; k < 4; k++)
            dstv[k] = make_float4(res[4 * k], res[4 * k + 1], res[4 * k + 2], res[4 * k + 3]);
    } else {
        // PB[lo] = Tq2[lo&15] @ Tq3[lo>>4];  W[(hi<<8)|lo][r] = sum_s PB[lo][r][s]*WA[hi][s]
        int lo = blk - 256, hi = t;
        As[t] = g_Tq[2][(lo & 15) * 256 + t];
        Bs[t] = g_Tq[3][(lo >> 4) * 256 + t];
        __syncthreads();
        float pb = 0.f;
#pragma unroll
        for (int s = 0; s < 16; s++) pb += As[r * 16 + s] * Bs[s * 16 + c];
        Pm[t] = pb;
        __syncthreads();

        const float4* wap = reinterpret_cast<const float4*>(&g_WA[hi * 16]);
        float4 w0 = wap[0], w1 = wap[1], w2 = wap[2], w3 = wap[3];
        float res[16];
#pragma unroll
        for (int rr = 0; rr < 16; rr++) {
            float4 m0 = PmV[rr * 4 + 0], m1 = PmV[rr * 4 + 1];
            float4 m2 = PmV[rr * 4 + 2], m3 = PmV[rr * 4 + 3];
            float a = m0.x * w0.x + m0.y * w0.y + m0.z * w0.z + m0.w * w0.w;
            a += m1.x * w1.x + m1.y * w1.y + m1.z * w1.z + m1.w * w1.w;
            a += m2.x * w2.x + m2.y * w2.y + m2.z * w2.z + m2.w * w2.w;
            a += m3.x * w3.x + m3.y * w3.y + m3.z * w3.z + m3.w * w3.w;
            res[rr] = a;
        }
        float4* dstv = reinterpret_cast<float4*>(&g_W[(((unsigned)hi << 8) | lo) * 16]);
#pragma unroll
        for (int k = 0; k < 4; k++)
            dstv[k] = make_float4(res[4 * k], res[4 * k + 1], res[4 * k + 2], res[4 * k + 3]);
    }
}

__global__ __launch_bounds__(256) void tt_main(const int* __restrict__ X,
                                               float* __restrict__ out) {
    int gtid = blockIdx.x * blockDim.x + threadIdx.x;
    int warp = gtid >> 5;
    int lane = threadIdx.x & 31;

    // Warp covers 32 consecutive batches; lane l loads X[b_i, l] (coalesced
    // 128B per iter); one ballot packs the whole 32-bit index.
    size_t base = (size_t)warp * 32 * 32;
    unsigned m = 0;
#pragma unroll
    for (int i = 0; i < 32; i++) {
        int x = __ldg(&X[base + (size_t)i * 32 + lane]);
        unsigned bm = __ballot_sync(0xFFFFFFFFu, x != 0);
        if (i == lane) m = bm;
    }
    unsigned pa = m & 0xFFFFu;
    unsigned ps = m >> 16;

    const float4* up = reinterpret_cast<const float4*>(&g_U[(size_t)pa * 16]);
    const float4* wp = reinterpret_cast<const float4*>(&g_W[(size_t)ps * 16]);
    float acc = 0.f;
#pragma unroll
    for (int k = 0; k < 4; k++) {
        float4 u = up[k];
        float4 w = wp[k];
        acc += u.x * w.x + u.y * w.y + u.z * w.z + u.w * w.w;
    }
    out[warp * 32 + lane] = acc;
}

extern "C" void kernel_launch(void* const* d_in, const int* in_sizes, int n_in,
                              void* d_out, int out_size) {
    const int* X = (const int*)d_in[0];
    const float* cf = (const float*)d_in[1];
    const float* cm = (const float*)d_in[2];
    const float* cl = (const float*)d_in[3];
    float* out = (float*)d_out;

    tt_A<<<98, 256>>>(cf, cm, cl);
    tt_A2<<<32, 256>>>();
    tt_B<<<512, 256>>>();
    tt_main<<<out_size / 256, 256>>>(X, out);
}

// round 11
// speedup vs baseline: 2.0811x; 1.1081x over previous
#include <cuda_runtime.h>
#include <cstdint>

// Tensor-train contraction, B=262144, D=32 binary cores, R=16.
// out[b] = v0(x0) @ M1..M30(x) @ w31(x31)
// 4-bit group tables:
//   uv4[16] = v0@M1@M2@M3 (bits0..3), TU[16]=M4..M7 (bits4..7)
//   Tq0..Tq3 [16] = M8..M11 / M12..M15 / M16..M19 / M20..M23
//   TW[16]=M24..M27 (bits24..27), wv4[16]=M28@M29@M30@w31 (bits28..31)
// A (fused): UA[lo8] = uv4[lo8&15] @ TU[lo8>>4]; WA[e8] = TW[e8&15] @ wv4[e8>>4]
// B: U[pa16] = UA[pa&255] @ (Tq0[(pa>>8)&15] @ Tq1[pa>>12])
//    W[ps16] = (Tq2[ps&15] @ Tq3[(ps>>4)&15]) @ WA[ps>>8]
// main: out[b] = dot(U[pa], W[ps])  (4 lanes cooperate per batch)

__device__ __align__(128) float g_Tq[4][16 * 256];
__device__ __align__(128) float g_UA[256 * 16];
__device__ __align__(128) float g_WA[256 * 16];
__device__ __align__(128) float g_U[65536 * 16];
__device__ __align__(128) float g_W[65536 * 16];

// cores_mid M_j (j=1..30): float2 cm2[(j-1)*256 + r*16 + s] = {bit0, bit1}
// core_first [0][r][bit] at cf[r*2+bit];  core_last [r][0][bit] at cl[r*2+bit]

// Grid 96 x 256:
//   blk 0..15  : UA block hi  (uv4 chain + TU[hi] chain + combine)
//   blk 16..31 : WA block b   (wv4 chain + TW[b] chain + combine)
//   blk 32..95 : Tq products, tbl=(blk-32)>>4, e=(blk-32)&15
__global__ __launch_bounds__(256) void tt_A(const float* __restrict__ cf,
                                            const float* __restrict__ cm,
                                            const float* __restrict__ cl) {
    __shared__ float sm[3648];
    const float2* cm2 = reinterpret_cast<const float2*>(cm);
    int blk = blockIdx.x;
    int tid = threadIdx.x;

    if (blk < 32) {
        // ---- fused vector-table blocks ----
        bool isU = blk < 16;
        int sel = isU ? blk : blk - 16;           // TU/TW combo index
        float* Mv = sm;                           // [jj][bit][s*16+r], 1536
        float* Msel = sm + 1536;                  // [jl][row*16+col], 1024
        float* V = sm + 2560;                     // ping-pong 2 x 272
        float* P = sm + 3104;                     // ping-pong 2 x 272

        // vector-chain matrices (both bit variants)
        for (int idx = tid; idx < 768; idx += 256) {
            int jj = idx >> 8;
            int rs = idx & 255;
            if (isU) {
                float2 v2 = cm2[jj * 256 + rs];          // M_{jj+1}[s][r], rs=s*16+r
                Mv[jj * 512 + rs] = v2.x;
                Mv[jj * 512 + 256 + rs] = v2.y;
            } else {
                int rr = rs >> 4, ss = rs & 15;
                float2 v2 = cm2[(29 - jj) * 256 + rs];   // M_{30-jj}[rr][ss]
                Mv[jj * 512 + ss * 16 + rr] = v2.x;
                Mv[jj * 512 + 256 + ss * 16 + rr] = v2.y;
            }
        }
        // selected TU/TW matrices
#pragma unroll
        for (int jl = 0; jl < 4; jl++) {
            float2 v2 = cm2[((isU ? 3 : 23) + jl) * 256 + tid];
            Msel[jl * 256 + tid] = ((sel >> jl) & 1) ? v2.y : v2.x;
        }
        int e = tid >> 4, r = tid & 15;
        V[e * 17 + r] = isU ? cf[r * 2 + (e & 1)] : cl[r * 2 + ((e >> 3) & 1)];
        P[e * 17 + r] = Msel[3 * 256 + tid];
        __syncthreads();

        int cur = 0;
        for (int jj = 0; jj < 3; jj++) {
            int bit = isU ? ((e >> (jj + 1)) & 1) : ((e >> (2 - jj)) & 1);
            const float* M = &Mv[jj * 512 + bit * 256];
            float a = 0.f;
#pragma unroll
            for (int s = 0; s < 16; s++) a += V[cur * 272 + e * 17 + s] * M[s * 16 + r];
            int jl = 2 - jj;
            float b = 0.f;
#pragma unroll
            for (int s = 0; s < 16; s++)
                b += Msel[jl * 256 + e * 16 + s] * P[cur * 272 + s * 17 + r];
            V[(cur ^ 1) * 272 + e * 17 + r] = a;
            P[(cur ^ 1) * 272 + e * 17 + r] = b;
            __syncthreads();
            cur ^= 1;
        }
        // combine
        if (isU) {
            // UA[hi*16+e][r] = sum_s uv4[e][s] * TU[s][r]
            float a = 0.f;
#pragma unroll
            for (int s = 0; s < 16; s++)
                a += V[cur * 272 + e * 17 + s] * P[cur * 272 + s * 17 + r];
            g_UA[(sel * 16 + e) * 16 + r] = a;
        } else {
            // WA[e*16+b][r] = sum_s TW[r][s] * wv4[e][s]
            float a = 0.f;
#pragma unroll
            for (int s = 0; s < 16; s++)
                a += P[cur * 272 + r * 17 + s] * V[cur * 272 + e * 17 + s];
            g_WA[(e * 16 + sel) * 16 + r] = a;
        }
    } else {
        // ---- Tq 4-chain products ----
        int pid = blk - 32;
        int tbl = pid >> 4, e = pid & 15;
        float* Msel = sm;                 // 1024
        float* P = sm + 1024;             // ping-pong 2 x 272
#pragma unroll
        for (int jl = 0; jl < 4; jl++) {
            float2 v2 = cm2[(7 + tbl * 4 + jl) * 256 + tid];
            Msel[jl * 256 + tid] = ((e >> jl) & 1) ? v2.y : v2.x;
        }
        int r = tid >> 4, c = tid & 15;
        P[r * 17 + c] = Msel[3 * 256 + tid];
        __syncthreads();
        int cur = 0;
        for (int jl = 2; jl >= 0; jl--) {
            float a = 0.f;
#pragma unroll
            for (int s = 0; s < 16; s++)
                a += Msel[jl * 256 + r * 16 + s] * P[cur * 272 + s * 17 + c];
            P[(cur ^ 1) * 272 + r * 17 + c] = a;
            __syncthreads();
            cur ^= 1;
        }
        g_Tq[tbl][e * 256 + tid] = P[cur * 272 + r * 17 + c];
    }
}

__global__ __launch_bounds__(256) void tt_B() {
    __shared__ float As[256];
    __shared__ float Bs[256];
    __shared__ __align__(16) float Pm[256];
    int blk = blockIdx.x;
    int t = threadIdx.x;
    int r = t >> 4, c = t & 15;
    const float4* PmV = reinterpret_cast<const float4*>(Pm);

    if (blk < 256) {
        // PA[hi] = Tq0[hi&15] @ Tq1[hi>>4];  U[(hi<<8)|lo][s] = sum_r UA[lo][r]*PA[r][s]
        int hi = blk, lo = t;
        As[t] = g_Tq[0][(hi & 15) * 256 + t];
        Bs[t] = g_Tq[1][(hi >> 4) * 256 + t];
        __syncthreads();
        float pa = 0.f;
#pragma unroll
        for (int s = 0; s < 16; s++) pa += As[r * 16 + s] * Bs[s * 16 + c];
        Pm[t] = pa;
        __syncthreads();

        const float4* uap = reinterpret_cast<const float4*>(&g_UA[lo * 16]);
        float u[16];
#pragma unroll
        for (int k = 0; k < 4; k++) {
            float4 q = uap[k];
            u[4 * k] = q.x; u[4 * k + 1] = q.y; u[4 * k + 2] = q.z; u[4 * k + 3] = q.w;
        }
        float res[16];
#pragma unroll
        for (int s = 0; s < 16; s++) res[s] = 0.f;
#pragma unroll
        for (int rr = 0; rr < 16; rr++) {
            float4 m0 = PmV[rr * 4 + 0], m1 = PmV[rr * 4 + 1];
            float4 m2 = PmV[rr * 4 + 2], m3 = PmV[rr * 4 + 3];
            float ur = u[rr];
            res[0] += ur * m0.x;  res[1] += ur * m0.y;  res[2] += ur * m0.z;  res[3] += ur * m0.w;
            res[4] += ur * m1.x;  res[5] += ur * m1.y;  res[6] += ur * m1.z;  res[7] += ur * m1.w;
            res[8] += ur * m2.x;  res[9] += ur * m2.y;  res[10] += ur * m2.z; res[11] += ur * m2.w;
            res[12] += ur * m3.x; res[13] += ur * m3.y; res[14] += ur * m3.z; res[15] += ur * m3.w;
        }
        float4* dstv = reinterpret_cast<float4*>(&g_U[(((unsigned)hi << 8) | lo) * 16]);
#pragma unroll
        for (int k = 0; k < 4; k++)
            dstv[k] = make_float4(res[4 * k], res[4 * k + 1], res[4 * k + 2], res[4 * k + 3]);
    } else {
        // PB[lo] = Tq2[lo&15] @ Tq3[lo>>4];  W[(hi<<8)|lo][r] = sum_s PB[r][s]*WA[hi][s]
        int lo = blk - 256, hi = t;
        As[t] = g_Tq[2][(lo & 15) * 256 + t];
        Bs[t] = g_Tq[3][(lo >> 4) * 256 + t];
        __syncthreads();
        float pb = 0.f;
#pragma unroll
        for (int s = 0; s < 16; s++) pb += As[r * 16 + s] * Bs[s * 16 + c];
        Pm[t] = pb;
        __syncthreads();

        const float4* wap = reinterpret_cast<const float4*>(&g_WA[hi * 16]);
        float4 w0 = wap[0], w1 = wap[1], w2 = wap[2], w3 = wap[3];
        float res[16];
#pragma unroll
        for (int rr = 0; rr < 16; rr++) {
            float4 m0 = PmV[rr * 4 + 0], m1 = PmV[rr * 4 + 1];
            float4 m2 = PmV[rr * 4 + 2], m3 = PmV[rr * 4 + 3];
            float a = m0.x * w0.x + m0.y * w0.y + m0.z * w0.z + m0.w * w0.w;
            a += m1.x * w1.x + m1.y * w1.y + m1.z * w1.z + m1.w * w1.w;
            a += m2.x * w2.x + m2.y * w2.y + m2.z * w2.z + m2.w * w2.w;
            a += m3.x * w3.x + m3.y * w3.y + m3.z * w3.z + m3.w * w3.w;
            res[rr] = a;
        }
        float4* dstv = reinterpret_cast<float4*>(&g_W[(((unsigned)hi << 8) | lo) * 16]);
#pragma unroll
        for (int k = 0; k < 4; k++)
            dstv[k] = make_float4(res[4 * k], res[4 * k + 1], res[4 * k + 2], res[4 * k + 3]);
    }
}

__global__ __launch_bounds__(256) void tt_main(const int* __restrict__ X,
                                               float* __restrict__ out) {
    int warpId = blockIdx.x * (blockDim.x >> 5) + (threadIdx.x >> 5);
    int lane = threadIdx.x & 31;

    // Phase 1: warp covers 32 batches; lane l loads X[b_i, l] (coalesced 128B),
    // one ballot packs the 32-bit index; lane i keeps batch i's mask.
    size_t base = (size_t)warpId * 32 * 32;
    unsigned m = 0;
#pragma unroll
    for (int i = 0; i < 32; i++) {
        int x = X[base + (size_t)i * 32 + lane];
        unsigned bm = __ballot_sync(0xFFFFFFFFu, x != 0);
        if (i == lane) m = bm;
    }

    // Phase 2: 4 lanes cooperate per batch (lane j loads float4 j of U and W),
    // 8 batches per pass, 4 passes. Gather lines/instr: 8 instead of 32.
    const float4* U4 = reinterpret_cast<const float4*>(g_U);
    const float4* W4 = reinterpret_cast<const float4*>(g_W);
    int j = lane & 3;
    int bq = lane >> 2;  // batch-within-pass 0..7

    unsigned pa[4], ps[4];
#pragma unroll
    for (int p = 0; p < 4; p++) {
        unsigned mm = __shfl_sync(0xFFFFFFFFu, m, p * 8 + bq);
        pa[p] = mm & 0xFFFFu;
        ps[p] = mm >> 16;
    }
    float4 uu[4], ww[4];
#pragma unroll
    for (int p = 0; p < 4; p++) {
        uu[p] = U4[pa[p] * 4 + j];
        ww[p] = W4[ps[p] * 4 + j];
    }
#pragma unroll
    for (int p = 0; p < 4; p++) {
        float4 u = uu[p], w = ww[p];
        float pd = u.x * w.x + u.y * w.y + u.z * w.z + u.w * w.w;
        pd += __shfl_xor_sync(0xFFFFFFFFu, pd, 1);
        pd += __shfl_xor_sync(0xFFFFFFFFu, pd, 2);
        if (j == 0) out[warpId * 32 + p * 8 + bq] = pd;
    }
}

extern "C" void kernel_launch(void* const* d_in, const int* in_sizes, int n_in,
                              void* d_out, int out_size) {
    const int* X = (const int*)d_in[0];
    const float* cf = (const float*)d_in[1];
    const float* cm = (const float*)d_in[2];
    const float* cl = (const float*)d_in[3];
    float* out = (float*)d_out;

    tt_A<<<96, 256>>>(cf, cm, cl);
    tt_B<<<512, 256>>>();
    tt_main<<<out_size / 256, 256>>>(X, out);
}